// round 12
// baseline (speedup 1.0000x reference)
#include <cuda_runtime.h>

// LSTM persistent kernel for GB300 (sm_103a).  R12.
// B=256, T=1024, D=128, H=256, C=10.
// 128 CTAs x 512 threads, software grid barrier per timestep.
// CTA owns 8 h-columns (all 4 gates) x 64 batch rows; Z = [h;x] @ W, K=384.
// R12 vs R10 (10307 us): ncu showed L1=52% -> SMEM-crossbar-wavefront bound
// (4 broadcast LDS.64 of W per k per warp = 6144 wasted wavefront-cycles).
//  - thread tile 2x8 -> 4x8 (rows x cols), 8-way K-split (48 k/quarter,
//    2 warps per quarter-tile: 16 row-groups x 2 col-groups per warp).
//    Per k per warp: 1 LDS.128 A (2 wf) + 2 LDS.128 W broadcast (2 wf)
//    for 16 FFMA2 -> GEMM crossbar 3072 cyc < 6144 fma floor.
//  - 8 partial-Z buffers (smem 221.8 KB, still 1 CTA/SM).

#define T_STEPS 1024
#define BATCH   256
#define DIM     128
#define HID     256
#define NCLS    10
#define GRID    128
#define NTHR    512
#define BM      64     // batch rows per CTA
#define HC      8      // h-columns per CTA
#define KTOT    384    // HID + DIM
#define NQ      8      // K-split ways
#define KQ      48     // K rows per quarter
#define HPAD    68     // hsh row stride (row = 64 floats; mult of 4 for LDS.128)
#define XPAD    129    // xsh row stride (row = 128 floats; odd)
#define ZPAD    33
#define CPAD    9

// Global state (no cudaMalloc allowed). Barrier tokens are monotone across
// launches/graph replays: flags and g_gen end each run equal.
__device__ float    g_h[2][HID * BATCH];
__device__ unsigned g_flag[GRID * 32];   // one token per CTA, 128B apart
__device__ unsigned g_gen;

// Accurate activations built on expf (safe even under --use_fast_math).
__device__ __forceinline__ float fsig(float z) {
    return 1.0f / (1.0f + expf(-z));
}
__device__ __forceinline__ float ftanh(float z) {
    float az = fabsf(z);
    float e  = expf(-2.0f * az);
    float t  = (1.0f - e) / (1.0f + e);
    return copysignf(t, z);
}

__device__ __forceinline__ unsigned long long pack_dup(float a) {
    unsigned long long r;
    asm("mov.b64 %0, {%1, %1};" : "=l"(r) : "f"(a));
    return r;
}
__device__ __forceinline__ void fma2(unsigned long long& acc,
                                     unsigned long long a,
                                     unsigned long long w) {
    asm("fma.rn.f32x2 %0, %1, %2, %0;" : "+l"(acc) : "l"(a), "l"(w));
}
__device__ __forceinline__ void unpack2(unsigned long long v, float& lo, float& hi) {
    asm("mov.b64 {%0, %1}, %2;" : "=f"(lo), "=f"(hi) : "l"(v));
}

__global__ void __launch_bounds__(NTHR, 1) lstm_persistent(
    const float* __restrict__ x,
    const float* __restrict__ wgx, const float* __restrict__ wgh, const float* __restrict__ bg,
    const float* __restrict__ wix, const float* __restrict__ wih, const float* __restrict__ bi,
    const float* __restrict__ wfx, const float* __restrict__ wfh, const float* __restrict__ bf,
    const float* __restrict__ wox, const float* __restrict__ woh, const float* __restrict__ bo,
    const float* __restrict__ wph, const float* __restrict__ bp,
    float* __restrict__ out)
{
    extern __shared__ float smem[];
    float* Wsh  = smem;                       // KTOT*32 resident weights
    float* hsh  = Wsh  + KTOT * 32;           // [k][r] staged h_prev
    float* xsh  = hsh  + HID * HPAD;          // [r][d] staged x_t
    float* zq0  = xsh  + BM * XPAD;           // NQ partial-Z buffers
    float* csh  = zq0  + NQ * BM * ZPAD;      // persistent cell state
    float* bsh  = csh  + BM * CPAD;           // 32 biases

    const int tid   = threadIdx.x;
    const int cta   = blockIdx.x;
    const int hj    = cta & 31;              // h-tile (32 tiles of 8 cols)
    const int bt    = cta >> 5;              // batch tile (4 tiles of 64 rows)
    const int b0    = bt * BM;
    const int jbase = hj * HC;

    const float* Wh[4] = {wgh, wih, wfh, woh};
    const float* Wx[4] = {wgx, wix, wfx, wox};
    const float* Bb[4] = {bg, bi, bf, bo};

    // ---- load resident weights: 32 cols (g0..7,i0..7,f0..7,o0..7) x K=384 ----
    for (int idx = tid; idx < KTOT * 32; idx += NTHR) {
        int k = idx >> 5, cc = idx & 31;
        int gate = cc >> 3, jj = cc & 7;
        int j = jbase + jj;
        float v = (k < HID) ? Wh[gate][k * HID + j]
                            : Wx[gate][(k - HID) * HID + j];
        Wsh[k * 32 + cc] = v;
    }
    if (tid < 32) {
        int gate = tid >> 3, jj = tid & 7;
        bsh[tid] = Bb[gate][jbase + jj];
    }
    for (int idx = tid; idx < BM * CPAD; idx += NTHR) csh[idx] = 0.0f;
    for (int idx = tid; idx < HC * BM; idx += NTHR) {
        int jj = idx >> 6, r = idx & 63;
        g_h[0][(jbase + jj) * BATCH + b0 + r] = 0.0f;
    }
    // prestage x_0
    {
        const float* xt = x + (size_t)b0 * T_STEPS * DIM;
        #pragma unroll 4
        for (int i = 0; i < 4; i++) {
            int lin = tid + NTHR * i;
            int r = lin >> 5, dq = lin & 31;
            float4 v = *(const float4*)(xt + (size_t)r * T_STEPS * DIM + dq * 4);
            float* dst = xsh + r * XPAD + dq * 4;
            dst[0] = v.x; dst[1] = v.y; dst[2] = v.z; dst[3] = v.w;
        }
    }

    // Barrier token base (g_gen advances only when every CTA has arrived).
    unsigned bar = *(volatile unsigned*)&g_gen;

    // ---- init grid barrier (flag-based) ----
    {
        bar++;
        __syncthreads();
        if (tid == 0) { __threadfence(); *(volatile unsigned*)&g_flag[cta * 32] = bar; }
        if (cta == 0) {
            if (tid < 32) {
                for (;;) {
                    unsigned m0 = *(volatile unsigned*)&g_flag[(tid      ) * 32];
                    unsigned m1 = *(volatile unsigned*)&g_flag[(tid + 32 ) * 32];
                    unsigned m2 = *(volatile unsigned*)&g_flag[(tid + 64 ) * 32];
                    unsigned m3 = *(volatile unsigned*)&g_flag[(tid + 96 ) * 32];
                    bool ok = (m0 >= bar) && (m1 >= bar) && (m2 >= bar) && (m3 >= bar);
                    if (__all_sync(0xffffffffu, ok)) break;
                    __nanosleep(32);
                }
                if (tid == 0) { __threadfence(); *(volatile unsigned*)&g_gen = bar; }
            }
        } else if (tid == 0) {
            while (*(volatile unsigned*)&g_gen < bar) __nanosleep(32);
            __threadfence();
        }
        __syncthreads();
    }

    // ---- GEMM mapping: 8 K-slices; each slice covers the 64x32 Z tile with
    // 64 threads (2 warps): 16 row-groups (4 rows) x 4 col-groups (8 cols).
    // slice q handles global k in [48q, 48(q+1)).
    const int q     = tid >> 6;             // 0..7
    const int qtid  = tid & 63;
    const int r0    = 4 * (qtid & 15);      // 4-row group
    const int cg    = qtid >> 4;            // 0..3
    const int cbase = cg * 8;
    float* zmine = zq0 + q * BM * ZPAD;
    const int klo_h = KQ * q;
    const int khi_h = (KQ * (q + 1) < HID) ? KQ * (q + 1) : HID;
    const int dlo   = (KQ * q       > HID) ? KQ * q       - HID : 0;
    const int dhi   = (KQ * (q + 1) > HID) ? KQ * (q + 1) - HID : 0;

    for (int t = 0; t < T_STEPS; t++) {
        const int rb = t & 1;

        // ---- stage h_prev (global [j][b] -> hsh[k][r]) ----
        const float* hb = g_h[rb];
        #pragma unroll 8
        for (int i = 0; i < 8; i++) {
            int lin = tid + NTHR * i;
            int k = lin >> 4, rq = lin & 15;
            float4 v = *(const float4*)(hb + k * BATCH + b0 + rq * 4);
            *(float4*)(hsh + k * HPAD + rq * 4) = v;
        }
        __syncthreads();

        // ---- partial Z over this slice's K range: 4 rows x 8 cols/thread ----
        unsigned long long acc[16];          // [row e][col-pair cp] = acc[4e+cp]
        if (q == 0) {
            #pragma unroll
            for (int cp = 0; cp < 4; cp++) {
                unsigned long long bb;
                asm("mov.b64 %0, {%1, %2};" : "=l"(bb)
                    : "f"(bsh[cbase + 2 * cp]), "f"(bsh[cbase + 2 * cp + 1]));
                acc[cp] = bb; acc[4 + cp] = bb; acc[8 + cp] = bb; acc[12 + cp] = bb;
            }
        } else {
            #pragma unroll
            for (int i = 0; i < 16; i++) acc[i] = 0ull;
        }

        #pragma unroll 2
        for (int k = klo_h; k < khi_h; k++) {
            float4 a4 = *(const float4*)(hsh + k * HPAD + r0);
            unsigned long long a0 = pack_dup(a4.x);
            unsigned long long a1 = pack_dup(a4.y);
            unsigned long long a2 = pack_dup(a4.z);
            unsigned long long a3 = pack_dup(a4.w);
            const ulonglong2* wp = (const ulonglong2*)(Wsh + k * 32 + cbase);
            ulonglong2 wA = wp[0];           // cols cbase+0..3
            ulonglong2 wB = wp[1];           // cols cbase+4..7
            fma2(acc[0],  a0, wA.x); fma2(acc[1],  a0, wA.y);
            fma2(acc[2],  a0, wB.x); fma2(acc[3],  a0, wB.y);
            fma2(acc[4],  a1, wA.x); fma2(acc[5],  a1, wA.y);
            fma2(acc[6],  a1, wB.x); fma2(acc[7],  a1, wB.y);
            fma2(acc[8],  a2, wA.x); fma2(acc[9],  a2, wA.y);
            fma2(acc[10], a2, wB.x); fma2(acc[11], a2, wB.y);
            fma2(acc[12], a3, wA.x); fma2(acc[13], a3, wA.y);
            fma2(acc[14], a3, wB.x); fma2(acc[15], a3, wB.y);
        }
        #pragma unroll 2
        for (int d = dlo; d < dhi; d++) {
            unsigned long long a0 = pack_dup(xsh[(r0 + 0) * XPAD + d]);
            unsigned long long a1 = pack_dup(xsh[(r0 + 1) * XPAD + d]);
            unsigned long long a2 = pack_dup(xsh[(r0 + 2) * XPAD + d]);
            unsigned long long a3 = pack_dup(xsh[(r0 + 3) * XPAD + d]);
            const ulonglong2* wp = (const ulonglong2*)(Wsh + (HID + d) * 32 + cbase);
            ulonglong2 wA = wp[0];
            ulonglong2 wB = wp[1];
            fma2(acc[0],  a0, wA.x); fma2(acc[1],  a0, wA.y);
            fma2(acc[2],  a0, wB.x); fma2(acc[3],  a0, wB.y);
            fma2(acc[4],  a1, wA.x); fma2(acc[5],  a1, wA.y);
            fma2(acc[6],  a1, wB.x); fma2(acc[7],  a1, wB.y);
            fma2(acc[8],  a2, wA.x); fma2(acc[9],  a2, wA.y);
            fma2(acc[10], a2, wB.x); fma2(acc[11], a2, wB.y);
            fma2(acc[12], a3, wA.x); fma2(acc[13], a3, wA.y);
            fma2(acc[14], a3, wB.x); fma2(acc[15], a3, wB.y);
        }
        // spill partial Z (4 rows x 8 cols)
        #pragma unroll
        for (int e = 0; e < 4; e++) {
            float* zr = zmine + (r0 + e) * ZPAD + cbase;
            #pragma unroll
            for (int cp = 0; cp < 4; cp++) {
                float lo, hi;
                unpack2(acc[4 * e + cp], lo, hi);
                zr[2 * cp]     = lo;
                zr[2 * cp + 1] = hi;
            }
        }
        __syncthreads();

        // ---- gates + state update + write h (coalesced, transposed) ----
        float* hn = g_h[rb ^ 1];
        {
            int jj = tid >> 6, r = tid & 63;  // 512 = 8 cols x 64 rows
            float zg = 0.0f, zi = 0.0f, zf = 0.0f, zo = 0.0f;
            #pragma unroll
            for (int p = 0; p < NQ; p++) {
                const float* zp = zq0 + p * BM * ZPAD + r * ZPAD;
                zg += zp[jj];
                zi += zp[8 + jj];
                zf += zp[16 + jj];
                zo += zp[24 + jj];
            }
            float g  = ftanh(zg);
            float ii = fsig(zi);
            float f  = fsig(zf);
            float o  = fsig(zo);
            float c  = csh[r * CPAD + jj];
            c = g * ii + c * f;
            csh[r * CPAD + jj] = c;
            hn[(jbase + jj) * BATCH + b0 + r] = ftanh(c) * o;
        }

        // ---- grid barrier with x_{t+1} prestage overlapped ----
        bar++;
        __syncthreads();                      // all h/z/c writes done CTA-wide
        if (tid == 0) { __threadfence(); *(volatile unsigned*)&g_flag[cta * 32] = bar; }
        // prestage next x while other CTAs finish (xsh dead since post-GEMM sync)
        if (t + 1 < T_STEPS) {
            const float* xt = x + (size_t)b0 * T_STEPS * DIM + (size_t)(t + 1) * DIM;
            #pragma unroll 4
            for (int i = 0; i < 4; i++) {
                int lin = tid + NTHR * i;
                int r = lin >> 5, dq = lin & 31;
                float4 v = *(const float4*)(xt + (size_t)r * T_STEPS * DIM + dq * 4);
                float* dst = xsh + r * XPAD + dq * 4;
                dst[0] = v.x; dst[1] = v.y; dst[2] = v.z; dst[3] = v.w;
            }
        }
        if (cta == 0) {
            if (tid < 32) {
                for (;;) {
                    unsigned m0 = *(volatile unsigned*)&g_flag[(tid      ) * 32];
                    unsigned m1 = *(volatile unsigned*)&g_flag[(tid + 32 ) * 32];
                    unsigned m2 = *(volatile unsigned*)&g_flag[(tid + 64 ) * 32];
                    unsigned m3 = *(volatile unsigned*)&g_flag[(tid + 96 ) * 32];
                    bool ok = (m0 >= bar) && (m1 >= bar) && (m2 >= bar) && (m3 >= bar);
                    if (__all_sync(0xffffffffu, ok)) break;
                    __nanosleep(32);
                }
                if (tid == 0) { __threadfence(); *(volatile unsigned*)&g_gen = bar; }
            }
        } else if (tid == 0) {
            while (*(volatile unsigned*)&g_gen < bar) __nanosleep(32);
            __threadfence();
        }
        __syncthreads();
    }

    // ---- final projection: out = h_T @ wph + bp (h_T is in buffer 0) ----
    if (hj == 0) {
        const float* hf = g_h[0];
        for (int idx = tid; idx < BM * NCLS; idx += NTHR) {
            int r = idx & 63, cls = idx >> 6;
            float s = bp[cls];
            #pragma unroll 4
            for (int j = 0; j < HID; j++)
                s += hf[j * BATCH + b0 + r] * wph[j * NCLS + cls];
            out[(b0 + r) * NCLS + cls] = s;
        }
    }
}

extern "C" void kernel_launch(void* const* d_in, const int* in_sizes, int n_in,
                              void* d_out, int out_size) {
    const float* xp  = (const float*)d_in[0];
    const float* wgx = (const float*)d_in[1];
    const float* wgh = (const float*)d_in[2];
    const float* bg  = (const float*)d_in[3];
    const float* wix = (const float*)d_in[4];
    const float* wih = (const float*)d_in[5];
    const float* bi  = (const float*)d_in[6];
    const float* wfx = (const float*)d_in[7];
    const float* wfh = (const float*)d_in[8];
    const float* bf  = (const float*)d_in[9];
    const float* wox = (const float*)d_in[10];
    const float* woh = (const float*)d_in[11];
    const float* bo  = (const float*)d_in[12];
    const float* wph = (const float*)d_in[13];
    const float* bp  = (const float*)d_in[14];
    float* out = (float*)d_out;

    const int smem_bytes =
        (KTOT * 32 + HID * HPAD + BM * XPAD + NQ * BM * ZPAD + BM * CPAD + 32) *
        (int)sizeof(float);

    cudaFuncSetAttribute(lstm_persistent,
                         cudaFuncAttributeMaxDynamicSharedMemorySize,
                         smem_bytes);

    lstm_persistent<<<GRID, NTHR, smem_bytes>>>(
        xp, wgx, wgh, bg, wix, wih, bi, wfx, wfh, bf, wox, woh, bo,
        wph, bp, out);
}

// round 13
// speedup vs baseline: 1.2463x; 1.2463x over previous
#include <cuda_runtime.h>

// LSTM persistent kernel for GB300 (sm_103a).  R13.
// B=256, T=1024, D=128, H=256, C=10.
// 128 CTAs x 512 threads. CTA owns 8 h-cols (all 4 gates) x 64 batch rows.
// R13 vs R10/R12: step time pinned ~10.3us while occ/L1/fma all moved ->
// serial latency (grid barrier + phase chain) dominates, not any pipe.
//  - x-part GEMM (x_t . Wx, no h dependence) + x prestage execute INSIDE the
//    barrier-wait window; acc registers carry across the wait into the h-part.
//  - per-batch-tile barriers: 4 independent groups of 32 CTAs (h only crosses
//    CTAs within a bt group). 32 flags = one aggregator warp, 1 flag/lane.
//  - GEMM shape reverted to R10's 2x8 tile, 4-way K-split; each quarter owns
//    64 h-rows + 32 x-cols so every warp has window work.

#define T_STEPS 1024
#define BATCH   256
#define DIM     128
#define HID     256
#define NCLS    10
#define GRID    128
#define NTHR    512
#define BM      64     // batch rows per CTA
#define HC      8      // h-columns per CTA
#define KTOT    384    // HID + DIM
#define NQ      4      // K-split ways
#define HPAD    68     // hsh row stride (row = 64 floats)
#define XPAD    129    // xsh row stride (row = 128 floats; odd)
#define ZPAD    33
#define CPAD    9

// Global state (no cudaMalloc allowed). Tokens are monotone across launches /
// graph replays: every flag and every genb end each run equal.
__device__ float    g_h[2][HID * BATCH];
__device__ unsigned g_flag[GRID * 32];   // per-CTA token, 128B apart
__device__ unsigned g_genb[4 * 32];      // per-bt-group gen, 128B apart

// Accurate activations built on expf (safe even under --use_fast_math).
__device__ __forceinline__ float fsig(float z) {
    return 1.0f / (1.0f + expf(-z));
}
__device__ __forceinline__ float ftanh(float z) {
    float az = fabsf(z);
    float e  = expf(-2.0f * az);
    float t  = (1.0f - e) / (1.0f + e);
    return copysignf(t, z);
}

__device__ __forceinline__ unsigned long long pack_dup(float a) {
    unsigned long long r;
    asm("mov.b64 %0, {%1, %1};" : "=l"(r) : "f"(a));
    return r;
}
__device__ __forceinline__ void fma2(unsigned long long& acc,
                                     unsigned long long a,
                                     unsigned long long w) {
    asm("fma.rn.f32x2 %0, %1, %2, %0;" : "+l"(acc) : "l"(a), "l"(w));
}
__device__ __forceinline__ void unpack2(unsigned long long v, float& lo, float& hi) {
    asm("mov.b64 {%0, %1}, %2;" : "=f"(lo), "=f"(hi) : "l"(v));
}

__global__ void __launch_bounds__(NTHR, 1) lstm_persistent(
    const float* __restrict__ x,
    const float* __restrict__ wgx, const float* __restrict__ wgh, const float* __restrict__ bg,
    const float* __restrict__ wix, const float* __restrict__ wih, const float* __restrict__ bi,
    const float* __restrict__ wfx, const float* __restrict__ wfh, const float* __restrict__ bf,
    const float* __restrict__ wox, const float* __restrict__ woh, const float* __restrict__ bo,
    const float* __restrict__ wph, const float* __restrict__ bp,
    float* __restrict__ out)
{
    extern __shared__ float smem[];
    float* Wsh  = smem;                       // KTOT*32 resident weights
    float* hsh  = Wsh  + KTOT * 32;           // [k][r] staged h_prev
    float* xsh0 = hsh  + HID * HPAD;          // x double buffer (parity 0)
    float* xsh1 = xsh0 + BM * XPAD;           // x double buffer (parity 1)
    float* zq0  = xsh1 + BM * XPAD;           // NQ partial-Z buffers
    float* csh  = zq0  + NQ * BM * ZPAD;      // persistent cell state
    float* bsh  = csh  + BM * CPAD;           // 32 biases

    const int tid   = threadIdx.x;
    const int cta   = blockIdx.x;
    const int hj    = cta & 31;              // h-tile (32 tiles of 8 cols)
    const int bt    = cta >> 5;              // batch tile (4 tiles of 64 rows)
    const int b0    = bt * BM;
    const int jbase = hj * HC;
    const bool agg  = (hj == 0);             // group aggregator CTA

    const float* Wh[4] = {wgh, wih, wfh, woh};
    const float* Wx[4] = {wgx, wix, wfx, wox};
    const float* Bb[4] = {bg, bi, bf, bo};

    // ---- load resident weights: 32 cols (g0..7,i0..7,f0..7,o0..7) x K=384 ----
    for (int idx = tid; idx < KTOT * 32; idx += NTHR) {
        int k = idx >> 5, cc = idx & 31;
        int gate = cc >> 3, jj = cc & 7;
        int j = jbase + jj;
        float v = (k < HID) ? Wh[gate][k * HID + j]
                            : Wx[gate][(k - HID) * HID + j];
        Wsh[k * 32 + cc] = v;
    }
    if (tid < 32) {
        int gate = tid >> 3, jj = tid & 7;
        bsh[tid] = Bb[gate][jbase + jj];
    }
    for (int idx = tid; idx < BM * CPAD; idx += NTHR) csh[idx] = 0.0f;
    for (int idx = tid; idx < HC * BM; idx += NTHR) {
        int jj = idx >> 6, r = idx & 63;
        g_h[0][(jbase + jj) * BATCH + b0 + r] = 0.0f;
    }
    // prestage x_0 into parity-0 buffer
    {
        const float* xt = x + (size_t)b0 * T_STEPS * DIM;
        #pragma unroll 4
        for (int i = 0; i < 4; i++) {
            int lin = tid + NTHR * i;
            int r = lin >> 5, dq = lin & 31;
            float4 v = *(const float4*)(xt + (size_t)r * T_STEPS * DIM + dq * 4);
            float* dst = xsh0 + r * XPAD + dq * 4;
            dst[0] = v.x; dst[1] = v.y; dst[2] = v.z; dst[3] = v.w;
        }
    }

    // Token base: g_genb settles at the common end value of the previous run.
    unsigned bar = *(volatile unsigned*)&g_genb[bt * 32];

    // ---- initial arrive (covers weights/x0/h0 init); wait happens in-loop ----
    bar++;
    __syncthreads();
    if (tid == 0) { __threadfence(); *(volatile unsigned*)&g_flag[cta * 32] = bar; }

    // ---- GEMM mapping: 4 K-quarters; quarter q owns h-rows [64q,64q+64) and
    // x-cols [32q,32q+32). Each quarter covers the 64x32 Z tile with 128
    // threads: 32 row-groups (2 rows) x 4 col-groups (8 cols).
    const int q     = tid >> 7;             // 0..3
    const int htid  = tid & 127;
    const int r0    = 2 * (htid & 31);
    const int cg    = htid >> 5;            // 0..3
    const int cbase = cg * 8;
    float* zmine = zq0 + q * BM * ZPAD;
    const int klo = 64 * q;
    const int dlo = 32 * q;

    for (int t = 0; t < T_STEPS; t++) {
        const int p = t & 1;
        const float* xcur = p ? xsh1 : xsh0;   // holds x_t
        float*       xnxt = p ? xsh0 : xsh1;   // gets x_{t+1}

        // ---- (window) x-part GEMM: acc = b + x_t[.,dlo:dlo+32] . Wx ----
        unsigned long long acc[8];
        if (q == 0) {
            #pragma unroll
            for (int cp = 0; cp < 4; cp++) {
                unsigned long long bb;
                asm("mov.b64 %0, {%1, %2};" : "=l"(bb)
                    : "f"(bsh[cbase + 2 * cp]), "f"(bsh[cbase + 2 * cp + 1]));
                acc[cp] = bb;
                acc[4 + cp] = bb;
            }
        } else {
            #pragma unroll
            for (int cp = 0; cp < 8; cp++) acc[cp] = 0ull;
        }
        #pragma unroll 4
        for (int dd = 0; dd < 32; dd++) {
            int d = dlo + dd;
            unsigned long long a0 = pack_dup(xcur[r0 * XPAD + d]);
            unsigned long long a1 = pack_dup(xcur[(r0 + 1) * XPAD + d]);
            const unsigned long long* wp =
                (const unsigned long long*)(Wsh + (HID + d) * 32 + cbase);
            #pragma unroll
            for (int cp = 0; cp < 4; cp++) {
                unsigned long long w = wp[cp];
                fma2(acc[cp],     a0, w);
                fma2(acc[4 + cp], a1, w);
            }
        }

        // ---- (window) prestage x_{t+1} ----
        if (t + 1 < T_STEPS) {
            const float* xt = x + (size_t)b0 * T_STEPS * DIM + (size_t)(t + 1) * DIM;
            #pragma unroll 4
            for (int i = 0; i < 4; i++) {
                int lin = tid + NTHR * i;
                int r = lin >> 5, dq = lin & 31;
                float4 v = *(const float4*)(xt + (size_t)r * T_STEPS * DIM + dq * 4);
                float* dst = xnxt + r * XPAD + dq * 4;
                dst[0] = v.x; dst[1] = v.y; dst[2] = v.z; dst[3] = v.w;
            }
        }

        // ---- barrier wait (token bar): h_t fully published by bt group ----
        if (agg) {
            if (tid < 32) {
                const volatile unsigned* fp = &g_flag[(bt * 32 + tid) * 32];
                while (!__all_sync(0xffffffffu, *fp >= bar)) { }
                if (tid == 0) {
                    __threadfence();
                    *(volatile unsigned*)&g_genb[bt * 32] = bar;
                }
            }
        } else if (tid == 0) {
            while (*(volatile unsigned*)&g_genb[bt * 32] < bar) { }
            __threadfence();
        }
        __syncthreads();

        // ---- stage h_t (global [j][b] -> hsh[k][r]) ----
        const float* hb = g_h[p];
        #pragma unroll 8
        for (int i = 0; i < 8; i++) {
            int lin = tid + NTHR * i;
            int k = lin >> 4, rq = lin & 15;
            float4 v = *(const float4*)(hb + k * BATCH + b0 + rq * 4);
            *(float4*)(hsh + k * HPAD + rq * 4) = v;
        }
        __syncthreads();

        // ---- h-part GEMM: k in [klo, klo+64) ----
        #pragma unroll 4
        for (int kk = 0; kk < 64; kk++) {
            int k = klo + kk;
            float2 a2 = *(const float2*)(hsh + k * HPAD + r0);
            unsigned long long a0 = pack_dup(a2.x);
            unsigned long long a1 = pack_dup(a2.y);
            const unsigned long long* wp =
                (const unsigned long long*)(Wsh + k * 32 + cbase);
            #pragma unroll
            for (int cp = 0; cp < 4; cp++) {
                unsigned long long w = wp[cp];
                fma2(acc[cp],     a0, w);
                fma2(acc[4 + cp], a1, w);
            }
        }
        // spill partial Z
        #pragma unroll
        for (int cp = 0; cp < 4; cp++) {
            float lo, hi;
            unpack2(acc[cp], lo, hi);
            zmine[r0 * ZPAD + cbase + 2 * cp]     = lo;
            zmine[r0 * ZPAD + cbase + 2 * cp + 1] = hi;
            unpack2(acc[4 + cp], lo, hi);
            zmine[(r0 + 1) * ZPAD + cbase + 2 * cp]     = lo;
            zmine[(r0 + 1) * ZPAD + cbase + 2 * cp + 1] = hi;
        }
        __syncthreads();

        // ---- gates + state update + write h_{t+1} (coalesced, transposed) ----
        float* hn = g_h[p ^ 1];
        {
            int jj = tid >> 6, r = tid & 63;  // 512 = 8 cols x 64 rows
            float zg = 0.0f, zi = 0.0f, zf = 0.0f, zo = 0.0f;
            #pragma unroll
            for (int pp = 0; pp < NQ; pp++) {
                const float* zp = zq0 + pp * BM * ZPAD + r * ZPAD;
                zg += zp[jj];
                zi += zp[8 + jj];
                zf += zp[16 + jj];
                zo += zp[24 + jj];
            }
            float g  = ftanh(zg);
            float ii = fsig(zi);
            float f  = fsig(zf);
            float o  = fsig(zo);
            float c  = csh[r * CPAD + jj];
            c = g * ii + c * f;
            csh[r * CPAD + jj] = c;
            hn[(jbase + jj) * BATCH + b0 + r] = ftanh(c) * o;
        }

        // ---- arrive: h_{t+1} published ----
        bar++;
        __syncthreads();                      // all STG h done CTA-wide
        if (tid == 0) { __threadfence(); *(volatile unsigned*)&g_flag[cta * 32] = bar; }
    }

    // ---- final: only hj==0 CTAs (aggregators) need h_T; publish genb for
    // replay-consistency, then project out = h_T @ wph + bp. h_T is in g_h[0].
    if (agg) {
        if (tid < 32) {
            const volatile unsigned* fp = &g_flag[(bt * 32 + tid) * 32];
            while (!__all_sync(0xffffffffu, *fp >= bar)) { }
            if (tid == 0) {
                __threadfence();
                *(volatile unsigned*)&g_genb[bt * 32] = bar;
            }
        }
        __syncthreads();
        const float* hf = g_h[0];
        for (int idx = tid; idx < BM * NCLS; idx += NTHR) {
            int r = idx & 63, cls = idx >> 6;
            float s = bp[cls];
            #pragma unroll 4
            for (int j = 0; j < HID; j++)
                s += hf[j * BATCH + b0 + r] * wph[j * NCLS + cls];
            out[(b0 + r) * NCLS + cls] = s;
        }
    }
}

extern "C" void kernel_launch(void* const* d_in, const int* in_sizes, int n_in,
                              void* d_out, int out_size) {
    const float* xp  = (const float*)d_in[0];
    const float* wgx = (const float*)d_in[1];
    const float* wgh = (const float*)d_in[2];
    const float* bg  = (const float*)d_in[3];
    const float* wix = (const float*)d_in[4];
    const float* wih = (const float*)d_in[5];
    const float* bi  = (const float*)d_in[6];
    const float* wfx = (const float*)d_in[7];
    const float* wfh = (const float*)d_in[8];
    const float* bf  = (const float*)d_in[9];
    const float* wox = (const float*)d_in[10];
    const float* woh = (const float*)d_in[11];
    const float* bo  = (const float*)d_in[12];
    const float* wph = (const float*)d_in[13];
    const float* bp  = (const float*)d_in[14];
    float* out = (float*)d_out;

    const int smem_bytes =
        (KTOT * 32 + HID * HPAD + 2 * BM * XPAD + NQ * BM * ZPAD + BM * CPAD + 32) *
        (int)sizeof(float);

    cudaFuncSetAttribute(lstm_persistent,
                         cudaFuncAttributeMaxDynamicSharedMemorySize,
                         smem_bytes);

    lstm_persistent<<<GRID, NTHR, smem_bytes>>>(
        xp, wgx, wgh, bg, wix, wih, bi, wfx, wfh, bf, wox, woh, bo,
        wph, bp, out);
}

// round 16
// speedup vs baseline: 1.2567x; 1.0083x over previous
#include <cuda_runtime.h>

// LSTM persistent kernel for GB300 (sm_103a).  R14.
// B=256, T=1024, D=128, H=256, C=10.
// 128 CTAs x 512 threads. CTA owns 8 h-cols (all 4 gates) x 64 batch rows.
// R14 = R13 overlap skeleton + R12 wavefront-lean GEMM tiles:
//  - ncu R13: L1=60.8% -> post-barrier h-GEMM crossbar-bound (6 wf/k/warp).
//  - 8 K-slices, 4x8 thread tile: slice q owns h-rows [32q,32q+32) AND
//    x-cols [16q,16q+16). Per k per warp: LDS.128 A (2wf) + 2x LDS.128 W
//    (2wf) = 4 wf -> h-GEMM crossbar 2048 < fma floor 4096 cyc.
//  - one acc set: bias -> x-part (in barrier window) -> h-part -> spill.
//  - single x buffer (sync inside window between x-GEMM and prestage),
//    smem 221.8 KB.
//  - per-bt-group barriers + monotone tokens as in R13.

#define T_STEPS 1024
#define BATCH   256
#define DIM     128
#define HID     256
#define NCLS    10
#define GRID    128
#define NTHR    512
#define BM      64     // batch rows per CTA
#define HC      8      // h-columns per CTA
#define KTOT    384    // HID + DIM
#define NQ      8      // K-split ways
#define HPAD    68     // hsh row stride (row = 64 floats; mult of 4)
#define XPAD    129    // xsh row stride (row = 128 floats; odd)
#define ZPAD    33
#define CPAD    9

// Global state (no cudaMalloc allowed). Tokens are monotone across launches /
// graph replays: every flag and every genb end each run equal.
__device__ float    g_h[2][HID * BATCH];
__device__ unsigned g_flag[GRID * 32];   // per-CTA token, 128B apart
__device__ unsigned g_genb[4 * 32];      // per-bt-group gen, 128B apart

// Accurate activations built on expf (safe even under --use_fast_math).
__device__ __forceinline__ float fsig(float z) {
    return 1.0f / (1.0f + expf(-z));
}
__device__ __forceinline__ float ftanh(float z) {
    float az = fabsf(z);
    float e  = expf(-2.0f * az);
    float t  = (1.0f - e) / (1.0f + e);
    return copysignf(t, z);
}

__device__ __forceinline__ unsigned long long pack_dup(float a) {
    unsigned long long r;
    asm("mov.b64 %0, {%1, %1};" : "=l"(r) : "f"(a));
    return r;
}
__device__ __forceinline__ void fma2(unsigned long long& acc,
                                     unsigned long long a,
                                     unsigned long long w) {
    asm("fma.rn.f32x2 %0, %1, %2, %0;" : "+l"(acc) : "l"(a), "l"(w));
}
__device__ __forceinline__ void unpack2(unsigned long long v, float& lo, float& hi) {
    asm("mov.b64 {%0, %1}, %2;" : "=f"(lo), "=f"(hi) : "l"(v));
}

__global__ void __launch_bounds__(NTHR, 1) lstm_persistent(
    const float* __restrict__ x,
    const float* __restrict__ wgx, const float* __restrict__ wgh, const float* __restrict__ bg,
    const float* __restrict__ wix, const float* __restrict__ wih, const float* __restrict__ bi,
    const float* __restrict__ wfx, const float* __restrict__ wfh, const float* __restrict__ bf,
    const float* __restrict__ wox, const float* __restrict__ woh, const float* __restrict__ bo,
    const float* __restrict__ wph, const float* __restrict__ bp,
    float* __restrict__ out)
{
    extern __shared__ float smem[];
    float* Wsh  = smem;                       // KTOT*32 resident weights
    float* hsh  = Wsh  + KTOT * 32;           // [k][r] staged h_prev
    float* xsh  = hsh  + HID * HPAD;          // [r][d] staged x_t (single buf)
    float* zq0  = xsh  + BM * XPAD;           // NQ partial-Z buffers
    float* csh  = zq0  + NQ * BM * ZPAD;      // persistent cell state
    float* bsh  = csh  + BM * CPAD;           // 32 biases

    const int tid   = threadIdx.x;
    const int cta   = blockIdx.x;
    const int hj    = cta & 31;              // h-tile (32 tiles of 8 cols)
    const int bt    = cta >> 5;              // batch tile (4 tiles of 64 rows)
    const int b0    = bt * BM;
    const int jbase = hj * HC;
    const bool agg  = (hj == 0);             // group aggregator CTA

    const float* Wh[4] = {wgh, wih, wfh, woh};
    const float* Wx[4] = {wgx, wix, wfx, wox};
    const float* Bb[4] = {bg, bi, bf, bo};

    // ---- load resident weights: 32 cols (g0..7,i0..7,f0..7,o0..7) x K=384 ----
    for (int idx = tid; idx < KTOT * 32; idx += NTHR) {
        int k = idx >> 5, cc = idx & 31;
        int gate = cc >> 3, jj = cc & 7;
        int j = jbase + jj;
        float v = (k < HID) ? Wh[gate][k * HID + j]
                            : Wx[gate][(k - HID) * HID + j];
        Wsh[k * 32 + cc] = v;
    }
    if (tid < 32) {
        int gate = tid >> 3, jj = tid & 7;
        bsh[tid] = Bb[gate][jbase + jj];
    }
    for (int idx = tid; idx < BM * CPAD; idx += NTHR) csh[idx] = 0.0f;
    for (int idx = tid; idx < HC * BM; idx += NTHR) {
        int jj = idx >> 6, r = idx & 63;
        g_h[0][(jbase + jj) * BATCH + b0 + r] = 0.0f;
    }
    // prestage x_0
    {
        const float* xt = x + (size_t)b0 * T_STEPS * DIM;
        #pragma unroll 4
        for (int i = 0; i < 4; i++) {
            int lin = tid + NTHR * i;
            int r = lin >> 5, dq = lin & 31;
            float4 v = *(const float4*)(xt + (size_t)r * T_STEPS * DIM + dq * 4);
            float* dst = xsh + r * XPAD + dq * 4;
            dst[0] = v.x; dst[1] = v.y; dst[2] = v.z; dst[3] = v.w;
        }
    }

    // Token base: g_genb settles at the common end value of the previous run.
    unsigned bar = *(volatile unsigned*)&g_genb[bt * 32];

    // ---- initial arrive (covers weights/x0/h0 init); wait happens in-loop ----
    bar++;
    __syncthreads();
    if (tid == 0) { __threadfence(); *(volatile unsigned*)&g_flag[cta * 32] = bar; }

    // ---- GEMM mapping: 8 K-slices; slice q owns h-rows [32q,32q+32) and
    // x-cols [16q,16q+16). Each slice covers the 64x32 Z tile with 64 threads
    // (2 warps): 16 row-groups (4 rows) x 4 col-groups (8 cols).
    const int q     = tid >> 6;             // 0..7
    const int qtid  = tid & 63;
    const int r0    = 4 * (qtid & 15);      // 4-row group
    const int cg    = qtid >> 4;            // 0..3
    const int cbase = cg * 8;
    float* zmine = zq0 + q * BM * ZPAD;
    const int klo = 32 * q;                 // h rows for this slice
    const int dlo = 16 * q;                 // x cols for this slice

    for (int t = 0; t < T_STEPS; t++) {
        const int p = t & 1;

        // ---- (window) x-part GEMM: acc = b + x_t[., dlo:dlo+16] . Wx ----
        unsigned long long acc[16];          // [row e][col-pair cp] = acc[4e+cp]
        if (q == 0) {
            #pragma unroll
            for (int cp = 0; cp < 4; cp++) {
                unsigned long long bb;
                asm("mov.b64 %0, {%1, %2};" : "=l"(bb)
                    : "f"(bsh[cbase + 2 * cp]), "f"(bsh[cbase + 2 * cp + 1]));
                acc[cp] = bb; acc[4 + cp] = bb; acc[8 + cp] = bb; acc[12 + cp] = bb;
            }
        } else {
            #pragma unroll
            for (int i = 0; i < 16; i++) acc[i] = 0ull;
        }
        #pragma unroll 2
        for (int dd = 0; dd < 16; dd++) {
            int d = dlo + dd;
            unsigned long long a0 = pack_dup(xsh[(r0 + 0) * XPAD + d]);
            unsigned long long a1 = pack_dup(xsh[(r0 + 1) * XPAD + d]);
            unsigned long long a2 = pack_dup(xsh[(r0 + 2) * XPAD + d]);
            unsigned long long a3 = pack_dup(xsh[(r0 + 3) * XPAD + d]);
            const ulonglong2* wp = (const ulonglong2*)(Wsh + (HID + d) * 32 + cbase);
            ulonglong2 wA = wp[0];
            ulonglong2 wB = wp[1];
            fma2(acc[0],  a0, wA.x); fma2(acc[1],  a0, wA.y);
            fma2(acc[2],  a0, wB.x); fma2(acc[3],  a0, wB.y);
            fma2(acc[4],  a1, wA.x); fma2(acc[5],  a1, wA.y);
            fma2(acc[6],  a1, wB.x); fma2(acc[7],  a1, wB.y);
            fma2(acc[8],  a2, wA.x); fma2(acc[9],  a2, wA.y);
            fma2(acc[10], a2, wB.x); fma2(acc[11], a2, wB.y);
            fma2(acc[12], a3, wA.x); fma2(acc[13], a3, wA.y);
            fma2(acc[14], a3, wB.x); fma2(acc[15], a3, wB.y);
        }
        __syncthreads();                      // all x_t reads done

        // ---- (window) prestage x_{t+1} into the same buffer ----
        if (t + 1 < T_STEPS) {
            const float* xt = x + (size_t)b0 * T_STEPS * DIM + (size_t)(t + 1) * DIM;
            #pragma unroll 4
            for (int i = 0; i < 4; i++) {
                int lin = tid + NTHR * i;
                int r = lin >> 5, dq = lin & 31;
                float4 v = *(const float4*)(xt + (size_t)r * T_STEPS * DIM + dq * 4);
                float* dst = xsh + r * XPAD + dq * 4;
                dst[0] = v.x; dst[1] = v.y; dst[2] = v.z; dst[3] = v.w;
            }
        }

        // ---- barrier wait (token bar): h_t fully published by bt group ----
        if (agg) {
            if (tid < 32) {
                const volatile unsigned* fp = &g_flag[(bt * 32 + tid) * 32];
                while (!__all_sync(0xffffffffu, *fp >= bar)) { }
                if (tid == 0) {
                    __threadfence();
                    *(volatile unsigned*)&g_genb[bt * 32] = bar;
                }
            }
        } else if (tid == 0) {
            while (*(volatile unsigned*)&g_genb[bt * 32] < bar) { }
            __threadfence();
        }
        __syncthreads();

        // ---- stage h_t (global [j][b] -> hsh[k][r]) ----
        const float* hb = g_h[p];
        #pragma unroll 8
        for (int i = 0; i < 8; i++) {
            int lin = tid + NTHR * i;
            int k = lin >> 4, rq = lin & 15;
            float4 v = *(const float4*)(hb + k * BATCH + b0 + rq * 4);
            *(float4*)(hsh + k * HPAD + rq * 4) = v;
        }
        __syncthreads();

        // ---- h-part GEMM: k in [klo, klo+32), 4x8 tile ----
        #pragma unroll 2
        for (int kk = 0; kk < 32; kk++) {
            int k = klo + kk;
            float4 a4 = *(const float4*)(hsh + k * HPAD + r0);
            unsigned long long a0 = pack_dup(a4.x);
            unsigned long long a1 = pack_dup(a4.y);
            unsigned long long a2 = pack_dup(a4.z);
            unsigned long long a3 = pack_dup(a4.w);
            const ulonglong2* wp = (const ulonglong2*)(Wsh + k * 32 + cbase);
            ulonglong2 wA = wp[0];
            ulonglong2 wB = wp[1];
            fma2(acc[0],  a0, wA.x); fma2(acc[1],  a0, wA.y);
            fma2(acc[2],  a0, wB.x); fma2(acc[3],  a0, wB.y);
            fma2(acc[4],  a1, wA.x); fma2(acc[5],  a1, wA.y);
            fma2(acc[6],  a1, wB.x); fma2(acc[7],  a1, wB.y);
            fma2(acc[8],  a2, wA.x); fma2(acc[9],  a2, wA.y);
            fma2(acc[10], a2, wB.x); fma2(acc[11], a2, wB.y);
            fma2(acc[12], a3, wA.x); fma2(acc[13], a3, wA.y);
            fma2(acc[14], a3, wB.x); fma2(acc[15], a3, wB.y);
        }
        // spill partial Z (4 rows x 8 cols)
        #pragma unroll
        for (int e = 0; e < 4; e++) {
            float* zr = zmine + (r0 + e) * ZPAD + cbase;
            #pragma unroll
            for (int cp = 0; cp < 4; cp++) {
                float lo, hi;
                unpack2(acc[4 * e + cp], lo, hi);
                zr[2 * cp]     = lo;
                zr[2 * cp + 1] = hi;
            }
        }
        __syncthreads();

        // ---- gates + state update + write h_{t+1} (coalesced, transposed) ----
        float* hn = g_h[p ^ 1];
        {
            int jj = tid >> 6, r = tid & 63;  // 512 = 8 cols x 64 rows
            float zg = 0.0f, zi = 0.0f, zf = 0.0f, zo = 0.0f;
            #pragma unroll
            for (int pp = 0; pp < NQ; pp++) {
                const float* zp = zq0 + pp * BM * ZPAD + r * ZPAD;
                zg += zp[jj];
                zi += zp[8 + jj];
                zf += zp[16 + jj];
                zo += zp[24 + jj];
            }
            float g  = ftanh(zg);
            float ii = fsig(zi);
            float f  = fsig(zf);
            float o  = fsig(zo);
            float c  = csh[r * CPAD + jj];
            c = g * ii + c * f;
            csh[r * CPAD + jj] = c;
            hn[(jbase + jj) * BATCH + b0 + r] = ftanh(c) * o;
        }

        // ---- arrive: h_{t+1} published ----
        bar++;
        __syncthreads();                      // all STG h done CTA-wide
        if (tid == 0) { __threadfence(); *(volatile unsigned*)&g_flag[cta * 32] = bar; }
    }

    // ---- final: aggregators wait for h_T, publish genb (replay-consistent),
    // then project out = h_T @ wph + bp. h_T lives in g_h[0] (T even).
    if (agg) {
        if (tid < 32) {
            const volatile unsigned* fp = &g_flag[(bt * 32 + tid) * 32];
            while (!__all_sync(0xffffffffu, *fp >= bar)) { }
            if (tid == 0) {
                __threadfence();
                *(volatile unsigned*)&g_genb[bt * 32] = bar;
            }
        }
        __syncthreads();
        const float* hf = g_h[0];
        for (int idx = tid; idx < BM * NCLS; idx += NTHR) {
            int r = idx & 63, cls = idx >> 6;
            float s = bp[cls];
            #pragma unroll 4
            for (int j = 0; j < HID; j++)
                s += hf[j * BATCH + b0 + r] * wph[j * NCLS + cls];
            out[(b0 + r) * NCLS + cls] = s;
        }
    }
}

extern "C" void kernel_launch(void* const* d_in, const int* in_sizes, int n_in,
                              void* d_out, int out_size) {
    const float* xp  = (const float*)d_in[0];
    const float* wgx = (const float*)d_in[1];
    const float* wgh = (const float*)d_in[2];
    const float* bg  = (const float*)d_in[3];
    const float* wix = (const float*)d_in[4];
    const float* wih = (const float*)d_in[5];
    const float* bi  = (const float*)d_in[6];
    const float* wfx = (const float*)d_in[7];
    const float* wfh = (const float*)d_in[8];
    const float* bf  = (const float*)d_in[9];
    const float* wox = (const float*)d_in[10];
    const float* woh = (const float*)d_in[11];
    const float* bo  = (const float*)d_in[12];
    const float* wph = (const float*)d_in[13];
    const float* bp  = (const float*)d_in[14];
    float* out = (float*)d_out;

    const int smem_bytes =
        (KTOT * 32 + HID * HPAD + BM * XPAD + NQ * BM * ZPAD + BM * CPAD + 32) *
        (int)sizeof(float);

    cudaFuncSetAttribute(lstm_persistent,
                         cudaFuncAttributeMaxDynamicSharedMemorySize,
                         smem_bytes);

    lstm_persistent<<<GRID, NTHR, smem_bytes>>>(
        xp, wgx, wgh, bg, wix, wih, bi, wfx, wfh, bf, wox, woh, bo,
        wph, bp, out);
}